// round 8
// baseline (speedup 1.0000x reference)
#include <cuda_runtime.h>
#include <math.h>
#include <limits.h>

#define H 128
#define W 128
#define B 8
#define NBLK 32
#define RPB 4              // output rows per block
#define NTHR 1024
#define MAX_D2 (127*127 + 127*127)

// No global scratch, no barrier state: CTAs are fully independent.

__global__ void __launch_bounds__(NTHR, 1)
edt_kernel(const float* __restrict__ in, float* __restrict__ out) {
    const int tid = threadIdx.x;
    const int j   = tid & 127;    // column
    const int q   = tid >> 7;     // slot 0..7 (h-range owner)
    const int rbase = blockIdx.x * RPB;

    __shared__ unsigned long long s_mask[H][2];   // full 128x128-bit union mask
    __shared__ int   s_part[RPB][8][W];
    __shared__ float s_res[RPB][W];

    // ---------- Phase 1: build FULL union-mask bitmap (redundant per CTA) ----
    // Pass t covers rows [32t, 32t+32). Lane l covers j in [4l, 4l+4) (float4).
    {
        const int lane = tid & 31;
        const int rloc = tid >> 5;            // 0..31
        const float4* base = (const float4*)in;
#pragma unroll
        for (int t = 0; t < 4; t++) {
            int r = t * 32 + rloc;
            const float4* p = base + (r * W + lane * 4) / 4;
            float4 v = __ldg(p);
            float m0 = v.x, m1 = v.y, m2 = v.z, m3 = v.w;
#pragma unroll
            for (int b = 1; b < B; b++) {      // max over batches, then 1 compare
                float4 u = __ldg(p + b * (H * W / 4));
                m0 = fmaxf(m0, u.x); m1 = fmaxf(m1, u.y);
                m2 = fmaxf(m2, u.z); m3 = fmaxf(m3, u.w);
            }
            unsigned nib = (unsigned)(m0 > 0.5f)
                         | ((unsigned)(m1 > 0.5f) << 1)
                         | ((unsigned)(m2 > 0.5f) << 2)
                         | ((unsigned)(m3 > 0.5f) << 3);
            unsigned word = nib << ((lane & 7) * 4);
            // OR-combine nibbles across each 8-lane group -> one u32 word
            word |= __shfl_xor_sync(0xFFFFFFFFu, word, 1);
            word |= __shfl_xor_sync(0xFFFFFFFFu, word, 2);
            word |= __shfl_xor_sync(0xFFFFFFFFu, word, 4);
            if ((lane & 7) == 0)
                ((unsigned*)&s_mask[r][0])[lane >> 3] = word;  // word w = bits [32w,32w+32)
        }
    }
    __syncthreads();

    // ---------- Phase 2: slot q scans h in [16q,16q+16) --------------------
    // Nearest-set-bit distance computed ONCE per (h,j), reused for 4 rows.
    {
        const int hbase = q << 4;
        int best0 = INT_MAX, best1 = INT_MAX, best2 = INT_MAX, best3 = INT_MAX;
#pragma unroll 4
        for (int k = 0; k < 16; k++) {
            int h = hbase + k;
            unsigned long long lo = s_mask[h][0];   // bits 0..63 (LDS broadcast)
            unsigned long long hi = s_mask[h][1];   // bits 64..127
            int dr, dl;
            if (j < 64) {                            // warp-uniform branch
                unsigned long long t = lo >> j;
                dr = t ? (__ffsll((long long)t) - 1)
                       : (hi ? (64 - j) + __ffsll((long long)hi) - 1 : 1024);
                unsigned long long u = lo << (63 - j);
                dl = u ? __clzll((long long)u) : 1024;
            } else {
                unsigned long long t = hi >> (j - 64);
                dr = t ? (__ffsll((long long)t) - 1) : 1024;
                unsigned long long u = hi << (127 - j);
                dl = u ? __clzll((long long)u)
                       : (lo ? (j - 63) + __clzll((long long)lo) : 1024);
            }
            int d  = min(dl, dr);
            int gv = (d > 127) ? (1 << 28) : d * d;  // empty-row sentinel
            int d0 = rbase - h;
            int d1 = d0 + 1, d2 = d0 + 2, d3 = d0 + 3;
            best0 = min(best0, d0 * d0 + gv);
            best1 = min(best1, d1 * d1 + gv);
            best2 = min(best2, d2 * d2 + gv);
            best3 = min(best3, d3 * d3 + gv);
        }
        s_part[0][q][j] = best0;
        s_part[1][q][j] = best1;
        s_part[2][q][j] = best2;
        s_part[3][q][j] = best3;
    }
    __syncthreads();

    // ---------- Reduce 8 slots per row, sqrt ---------------------------------
    if (q < RPB) {
        int b8 = INT_MAX;
#pragma unroll
        for (int qq = 0; qq < 8; qq++)
            b8 = min(b8, s_part[q][qq][j]);
        s_res[q][j] = (b8 > MAX_D2) ? INFINITY : sqrtf((float)b8);
    }
    __syncthreads();

    // ---------- Broadcast write: thread (j,q) writes batch q, all 4 rows -----
#pragma unroll
    for (int r = 0; r < RPB; r++)
        out[q * (H * W) + (rbase + r) * W + j] = s_res[r][j];
}

extern "C" void kernel_launch(void* const* d_in, const int* in_sizes, int n_in,
                              void* d_out, int out_size) {
    const float* in = (const float*)d_in[0];
    float* out = (float*)d_out;
    edt_kernel<<<NBLK, NTHR>>>(in, out);
}

// round 9
// speedup vs baseline: 1.3201x; 1.3201x over previous
#include <cuda_runtime.h>
#include <math.h>
#include <limits.h>

#define H 128
#define W 128
#define B 8
#define NBLK 16            // one 16-CTA cluster covers all 128 rows
#define RPB 8              // rows per CTA
#define NTHR 1024
#define G_EMPTY 40000      // > MAX_D2, fits u16: empty-row sentinel
#define MAX_D2 (127*127 + 127*127)

// Cross-CTA 1D row-distance table (u16), exchanged through L2 within the cluster.
__device__ unsigned short g_G[H * W];

__global__ void __launch_bounds__(NTHR, 1) __cluster_dims__(NBLK, 1, 1)
edt_cluster(const float* __restrict__ in, float* __restrict__ out) {
    const int tid = threadIdx.x;
    const int j   = tid & 127;        // column 0..127
    const int q   = tid >> 7;         // slot 0..7
    const int rbase = blockIdx.x * RPB;
    const int row   = rbase + q;      // this thread's phase-1 row

    __shared__ unsigned s_mw[RPB][4];
    __shared__ int      s_part[RPB][8][W];
    __shared__ float    s_res[RPB][W];

    // ---------- Phase 1: union mask over batch for row (one thread per (row,j))
    {
        float m = __ldg(&in[row * W + j]);
#pragma unroll
        for (int b = 1; b < B; b++)
            m = fmaxf(m, __ldg(&in[b * (H * W) + row * W + j]));
        unsigned bal = __ballot_sync(0xFFFFFFFFu, m > 0.5f);
        if ((tid & 31) == 0)
            s_mw[q][(tid >> 5) & 3] = bal;    // warp w -> word (w&3) of row q=w>>2
    }
    __syncthreads();

    // Nearest set bit left/right of column j (once per (row,j)); store u16 G.
    {
        unsigned long long lo = s_mw[q][0] | ((unsigned long long)s_mw[q][1] << 32);
        unsigned long long hi = s_mw[q][2] | ((unsigned long long)s_mw[q][3] << 32);
        int dr, dl;
        if (j < 64) {                           // warp-uniform branch
            unsigned long long t = lo >> j;
            dr = t ? (__ffsll((long long)t) - 1)
                   : (hi ? (64 - j) + __ffsll((long long)hi) - 1 : 1024);
            unsigned long long u = lo << (63 - j);
            dl = u ? __clzll((long long)u) : 1024;
        } else {
            unsigned long long t = hi >> (j - 64);
            dr = t ? (__ffsll((long long)t) - 1) : 1024;
            unsigned long long u = hi << (127 - j);
            dl = u ? __clzll((long long)u)
                   : (lo ? (j - 63) + __clzll((long long)lo) : 1024);
        }
        int d = min(dl, dr);
        unsigned short gv = (d > 127) ? (unsigned short)G_EMPTY
                                      : (unsigned short)(d * d);
        __stcg(&g_G[row * W + j], gv);
    }

    // ---------- HW cluster barrier: arrive(release) + wait(acquire), ~0.3-0.5us
    asm volatile("barrier.cluster.arrive.aligned;" ::: "memory");
    asm volatile("barrier.cluster.wait.aligned;"   ::: "memory");

    // ---------- Phase 2: slot q scans h in [16q,16q+16); reuse gv for 8 rows --
    {
        const int hbase = q << 4;
        int gv[16];
#pragma unroll
        for (int k = 0; k < 16; k++)                       // batched: MLP=16
            gv[k] = (int)__ldcg(&g_G[(hbase + k) * W + j]);

        int best[RPB];
#pragma unroll
        for (int r = 0; r < RPB; r++) best[r] = INT_MAX;
#pragma unroll
        for (int k = 0; k < 16; k++) {
            int h = hbase + k;
#pragma unroll
            for (int r = 0; r < RPB; r++) {
                int d = rbase + r - h;
                best[r] = min(best[r], d * d + gv[k]);
            }
        }
#pragma unroll
        for (int r = 0; r < RPB; r++)
            s_part[r][q][j] = best[r];
    }
    __syncthreads();

    // ---------- Reduce 8 slots for row q, sqrt --------------------------------
    {
        int b8 = INT_MAX;
#pragma unroll
        for (int qq = 0; qq < 8; qq++)
            b8 = min(b8, s_part[q][qq][j]);
        s_res[q][j] = (b8 > MAX_D2) ? INFINITY : sqrtf((float)b8);
    }
    __syncthreads();

    // ---------- Broadcast: thread (j,q) writes batch q for all 8 rows ---------
#pragma unroll
    for (int r = 0; r < RPB; r++)
        out[q * (H * W) + (rbase + r) * W + j] = s_res[r][j];
}

extern "C" void kernel_launch(void* const* d_in, const int* in_sizes, int n_in,
                              void* d_out, int out_size) {
    const float* in = (const float*)d_in[0];
    float* out = (float*)d_out;
    // 16-CTA clusters exceed the portable max (8): opt in every call (idempotent).
    cudaFuncSetAttribute(edt_cluster,
                         cudaFuncAttributeNonPortableClusterSizeAllowed, 1);
    edt_cluster<<<NBLK, NTHR>>>(in, out);
}

// round 10
// speedup vs baseline: 1.4286x; 1.0821x over previous
#include <cuda_runtime.h>
#include <math.h>
#include <limits.h>

#define H 128
#define W 128
#define B 8
#define NBLK 128
#define NTHR 512
#define G_EMPTY 40000      // > MAX_D2, fits u16: empty-row sentinel
#define MAX_D2 (127*127 + 127*127)

// Cross-block 1D row-distance table (u16) + barrier counter.
__device__ unsigned short g_G[H * W];
__device__ unsigned g_bar = 0;

__global__ void __launch_bounds__(NTHR, 1)
edt_fused(const float* __restrict__ in, float* __restrict__ out) {
    const int tid = threadIdx.x;
    const int j   = tid & 127;   // column
    const int p   = tid >> 7;    // quarter 0..3
    const int row = blockIdx.x;  // phase 1: h ; phase 2: i

    __shared__ unsigned s_w[4];
    __shared__ int s_part[4][W];
    __shared__ float s_res[W];

    // ---------- Phase 1: mask ballot for this row (union over batch) ----------
    if (tid < 128) {
        bool m = false;
#pragma unroll
        for (int b = 0; b < B; b++)
            m |= in[b * (H * W) + row * W + j] > 0.5f;
        unsigned bal = __ballot_sync(0xFFFFFFFFu, m);
        if ((tid & 31) == 0) s_w[tid >> 5] = bal;
    }
    __syncthreads();

    // Nearest set bit left/right of column j (bit trick, once per (row,j)).
    if (tid < 128) {
        unsigned long long lo = s_w[0] | ((unsigned long long)s_w[1] << 32);
        unsigned long long hi = s_w[2] | ((unsigned long long)s_w[3] << 32);
        int dr, dl;
        if (j < 64) {                            // warp-uniform branch
            unsigned long long t = lo >> j;
            dr = t ? (__ffsll((long long)t) - 1)
                   : (hi ? (64 - j) + __ffsll((long long)hi) - 1 : 1024);
            unsigned long long u = lo << (63 - j);
            dl = u ? __clzll((long long)u) : 1024;
        } else {
            unsigned long long t = hi >> (j - 64);
            dr = t ? (__ffsll((long long)t) - 1) : 1024;
            unsigned long long u = hi << (127 - j);
            dl = u ? __clzll((long long)u)
                   : (lo ? (j - 63) + __clzll((long long)lo) : 1024);
        }
        int d = min(dl, dr);
        unsigned short gv = (d > 127) ? (unsigned short)G_EMPTY
                                      : (unsigned short)(d * d);
        __stcg(&g_G[row * W + j], gv);
    }

    // ---------- Grid barrier: release-atomic arrive, acquire-load poll --------
    // (no full MEMBAR.ALL.GPU drains on the critical path)
    __syncthreads();
    if (tid == 0) {
        unsigned ticket;
        asm volatile("atom.release.gpu.global.add.u32 %0, [%1], 1;"
                     : "=r"(ticket) : "l"(&g_bar) : "memory");
        unsigned target = (ticket / NBLK + 1u) * NBLK;  // generation-safe replays
        unsigned cur;
        do {
            asm volatile("ld.acquire.gpu.global.u32 %0, [%1];"
                         : "=r"(cur) : "l"(&g_bar) : "memory");
        } while (cur < target);
    }
    __syncthreads();

    // ---------- Phase 2: thread (j,p) scans h in [32p, 32p+32) ----------------
    {
        const int hbase = p << 5;
        int best = INT_MAX;
#pragma unroll
        for (int k = 0; k < 32; k++) {
            int h  = hbase + k;
            int dh = row - h;
            int gv = (int)__ldcg(&g_G[h * W + j]);   // coalesced u16, MLP=32
            best = min(best, dh * dh + gv);
        }
        s_part[p][j] = best;
    }
    __syncthreads();

    // ---------- Reduce quarters, sqrt, broadcast to all 8 batches --------------
    if (tid < 128) {
        int b4 = min(min(s_part[0][j], s_part[1][j]),
                     min(s_part[2][j], s_part[3][j]));
        s_res[j] = (b4 > MAX_D2) ? INFINITY : sqrtf((float)b4);
    }
    __syncthreads();
    {
        float r = s_res[j];
        out[(2 * p)     * (H * W) + row * W + j] = r;
        out[(2 * p + 1) * (H * W) + row * W + j] = r;
    }
}

extern "C" void kernel_launch(void* const* d_in, const int* in_sizes, int n_in,
                              void* d_out, int out_size) {
    const float* in = (const float*)d_in[0];
    float* out = (float*)d_out;
    edt_fused<<<NBLK, NTHR>>>(in, out);
}

// round 11
// speedup vs baseline: 1.4337x; 1.0036x over previous
#include <cuda_runtime.h>
#include <math.h>
#include <limits.h>

#define H 128
#define W 128
#define B 8
#define SENT (1 << 28)
#define NBLK 128
#define NTHR 512
#define MAX_D2 (127*127 + 127*127)

// Cross-block 1D row-distance table + barrier counter.
__device__ int g_G[H * W];
__device__ unsigned g_bar = 0;

__global__ void __launch_bounds__(NTHR, 1)
edt_fused(const float* __restrict__ in, float* __restrict__ out) {
    const int tid = threadIdx.x;
    const int j   = tid & 127;   // column
    const int p   = tid >> 7;    // quarter 0..3
    const int row = blockIdx.x;  // phase 1: h ; phase 2: i

    __shared__ unsigned s_w[4];
    __shared__ int s_part[4][W];
    __shared__ float s_res[W];

    // ---------- Phase 1: mask ballot for this row (union over batch) ----------
    if (tid < 128) {
        bool m = false;
#pragma unroll
        for (int b = 0; b < B; b++)
            m |= in[b * (H * W) + row * W + j] > 0.5f;
        unsigned bal = __ballot_sync(0xFFFFFFFFu, m);
        if ((tid & 31) == 0) s_w[tid >> 5] = bal;
    }
    __syncthreads();

    // Nearest set bit left/right of column j (~20 instr, replaces 32-iter scan).
    if (tid < 128) {
        unsigned long long lo = s_w[0] | ((unsigned long long)s_w[1] << 32);
        unsigned long long hi = s_w[2] | ((unsigned long long)s_w[3] << 32);
        int dr, dl;
        if (j < 64) {                            // warp-uniform branch
            unsigned long long t = lo >> j;
            dr = t ? (__ffsll((long long)t) - 1)
                   : (hi ? (64 - j) + __ffsll((long long)hi) - 1 : 1024);
            unsigned long long u = lo << (63 - j);
            dl = u ? __clzll((long long)u) : 1024;
        } else {
            unsigned long long t = hi >> (j - 64);
            dr = t ? (__ffsll((long long)t) - 1) : 1024;
            unsigned long long u = hi << (127 - j);
            dl = u ? __clzll((long long)u)
                   : (lo ? (j - 63) + __clzll((long long)lo) : 1024);
        }
        int d = min(dl, dr);
        int gv = (d > 127) ? SENT : d * d;
        __stcg(&g_G[row * W + j], gv);           // int32, L2-visible
    }

    // ---------- Grid barrier: R3-proven (fence + relaxed atomic + volatile poll)
    __threadfence();   // release g_G writes to GPU scope
    __syncthreads();
    if (tid == 0) {
        unsigned ticket = atomicAdd(&g_bar, 1u);
        unsigned target = (ticket / NBLK + 1u) * NBLK;  // generation-safe replays
        volatile unsigned* vb = &g_bar;
        while (*vb < target) { }
        __threadfence();  // acquire before consuming g_G
    }
    __syncthreads();

    // ---------- Phase 2: thread (j,p) scans h in [32p, 32p+32) ----------------
    {
        const int hbase = p << 5;
        const int* gcol = g_G + j;
        int best = SENT;
#pragma unroll
        for (int k = 0; k < 32; k++) {
            int h = hbase + k;
            int d = row - h;
            best = min(best, d * d + __ldcg(gcol + h * W));  // coalesced, MLP=32
        }
        s_part[p][j] = best;
    }
    __syncthreads();

    // ---------- Reduce quarters, sqrt, broadcast to all 8 batches --------------
    if (tid < 128) {
        int b4 = min(min(s_part[0][j], s_part[1][j]),
                     min(s_part[2][j], s_part[3][j]));
        s_res[j] = (b4 >= SENT) ? INFINITY : sqrtf((float)b4);
    }
    __syncthreads();
    {
        float r = s_res[j];
        out[(2 * p)     * (H * W) + row * W + j] = r;
        out[(2 * p + 1) * (H * W) + row * W + j] = r;
    }
}

extern "C" void kernel_launch(void* const* d_in, const int* in_sizes, int n_in,
                              void* d_out, int out_size) {
    const float* in = (const float*)d_in[0];
    float* out = (float*)d_out;
    edt_fused<<<NBLK, NTHR>>>(in, out);
}

// round 12
// speedup vs baseline: 1.4493x; 1.0109x over previous
#include <cuda_runtime.h>
#include <math.h>
#include <limits.h>

#define H 128
#define W 128
#define B 8
#define SENT (1 << 28)
#define NBLK 128
#define NTHR 512
#define MAX_D2 (127*127 + 127*127)

// Cross-block 1D row-distance table + barrier counter.
__device__ int g_G[H * W];
__device__ unsigned g_bar = 0;

__global__ void __launch_bounds__(NTHR, 1)
edt_fused(const float* __restrict__ in, float* __restrict__ out) {
    const int tid = threadIdx.x;
    const int j   = tid & 127;   // column
    const int p   = tid >> 7;    // quarter 0..3
    const int row = blockIdx.x;  // phase 1: h ; phase 2: i

    __shared__ unsigned s_w[4];
    __shared__ int s_part[4][W];
    __shared__ float s_res[W];

    // ---------- Phase 1: mask ballot for this row (union over batch) ----------
    if (tid < 128) {
        bool m = false;
#pragma unroll
        for (int b = 0; b < B; b++)
            m |= in[b * (H * W) + row * W + j] > 0.5f;
        unsigned bal = __ballot_sync(0xFFFFFFFFu, m);
        if ((tid & 31) == 0) s_w[tid >> 5] = bal;
    }
    __syncthreads();

    // Nearest set bit left/right of column j (~20 instr bit trick).
    if (tid < 128) {
        unsigned long long lo = s_w[0] | ((unsigned long long)s_w[1] << 32);
        unsigned long long hi = s_w[2] | ((unsigned long long)s_w[3] << 32);
        int dr, dl;
        if (j < 64) {                            // warp-uniform branch
            unsigned long long t = lo >> j;
            dr = t ? (__ffsll((long long)t) - 1)
                   : (hi ? (64 - j) + __ffsll((long long)hi) - 1 : 1024);
            unsigned long long u = lo << (63 - j);
            dl = u ? __clzll((long long)u) : 1024;
        } else {
            unsigned long long t = hi >> (j - 64);
            dr = t ? (__ffsll((long long)t) - 1) : 1024;
            unsigned long long u = hi << (127 - j);
            dl = u ? __clzll((long long)u)
                   : (lo ? (j - 63) + __clzll((long long)lo) : 1024);
        }
        int d = min(dl, dr);
        int gv = (d > 127) ? SENT : d * d;
        __stcg(&g_G[row * W + j], gv);           // int32, L2-visible
    }

    // ---------- Grid barrier: ONE membar per CTA (cooperative-groups pattern) --
    __syncthreads();   // orders all block stores before thread 0's fence
    if (tid == 0) {
        __threadfence();                         // single cumulative release
        unsigned ticket = atomicAdd(&g_bar, 1u);
        unsigned target = (ticket / NBLK + 1u) * NBLK;  // generation-safe replays
        volatile unsigned* vb = &g_bar;
        while (*vb < target) { }
        __threadfence();                         // acquire before consuming g_G
    }
    __syncthreads();

    // ---------- Phase 2: thread (j,p) scans h in [32p, 32p+32) ----------------
    {
        const int hbase = p << 5;
        const int* gcol = g_G + j;
        int best = SENT;
#pragma unroll
        for (int k = 0; k < 32; k++) {
            int h = hbase + k;
            int d = row - h;
            best = min(best, d * d + __ldcg(gcol + h * W));  // coalesced, MLP=32
        }
        s_part[p][j] = best;
    }
    __syncthreads();

    // ---------- Reduce quarters, sqrt, broadcast to all 8 batches --------------
    if (tid < 128) {
        int b4 = min(min(s_part[0][j], s_part[1][j]),
                     min(s_part[2][j], s_part[3][j]));
        s_res[j] = (b4 >= SENT) ? INFINITY : sqrtf((float)b4);
    }
    __syncthreads();
    {
        float r = s_res[j];
        out[(2 * p)     * (H * W) + row * W + j] = r;
        out[(2 * p + 1) * (H * W) + row * W + j] = r;
    }
}

extern "C" void kernel_launch(void* const* d_in, const int* in_sizes, int n_in,
                              void* d_out, int out_size) {
    const float* in = (const float*)d_in[0];
    float* out = (float*)d_out;
    edt_fused<<<NBLK, NTHR>>>(in, out);
}

// round 13
// speedup vs baseline: 1.5094x; 1.0415x over previous
#include <cuda_runtime.h>
#include <math.h>
#include <limits.h>

#define H 128
#define W 128
#define B 8
#define G_EMPTY 40000      // > MAX_D2, fits u16: empty-row sentinel
#define MAX_D2 (127*127 + 127*127)

// Cross-kernel 1D row-distance table (u16).
__device__ unsigned short g_G[H * W];

// ---------- K1: per-row union mask -> nearest-set-bit distance -> g_G --------
__global__ void __launch_bounds__(128, 1)
edt_g(const float* __restrict__ in) {
    const int j   = threadIdx.x;
    const int row = blockIdx.x;

#if __CUDA_ARCH__ >= 900
    // Let the dependent grid begin its launch ramp immediately; correctness is
    // gated by cudaGridDependencySynchronize() in K2 (waits for K1 completion).
    cudaTriggerProgrammaticLaunchCompletion();
#endif

    __shared__ unsigned s_w[4];

    float m = __ldg(&in[row * W + j]);
#pragma unroll
    for (int b = 1; b < B; b++)
        m = fmaxf(m, __ldg(&in[b * (H * W) + row * W + j]));
    unsigned bal = __ballot_sync(0xFFFFFFFFu, m > 0.5f);
    if ((j & 31) == 0) s_w[j >> 5] = bal;
    __syncthreads();

    unsigned long long lo = s_w[0] | ((unsigned long long)s_w[1] << 32);
    unsigned long long hi = s_w[2] | ((unsigned long long)s_w[3] << 32);
    int dr, dl;
    if (j < 64) {                            // warp-uniform branch
        unsigned long long t = lo >> j;
        dr = t ? (__ffsll((long long)t) - 1)
               : (hi ? (64 - j) + __ffsll((long long)hi) - 1 : 1024);
        unsigned long long u = lo << (63 - j);
        dl = u ? __clzll((long long)u) : 1024;
    } else {
        unsigned long long t = hi >> (j - 64);
        dr = t ? (__ffsll((long long)t) - 1) : 1024;
        unsigned long long u = hi << (127 - j);
        dl = u ? __clzll((long long)u)
               : (lo ? (j - 63) + __clzll((long long)lo) : 1024);
    }
    int d = min(dl, dr);
    g_G[row * W + j] = (d > 127) ? (unsigned short)G_EMPTY
                                 : (unsigned short)(d * d);
}

// ---------- K2 (PDL secondary): column pass + sqrt + broadcast ----------------
__global__ void __launch_bounds__(512, 1)
edt_d(float* __restrict__ out) {
    const int tid = threadIdx.x;
    const int j   = tid & 127;   // column
    const int p   = tid >> 7;    // quarter 0..3
    const int row = blockIdx.x;  // output row i

    __shared__ int s_part[4][W];
    __shared__ float s_res[W];

#if __CUDA_ARCH__ >= 900
    cudaGridDependencySynchronize();   // K1 done + g_G visible
#endif

    {
        const int hbase = p << 5;
        int best = INT_MAX;
#pragma unroll
        for (int k = 0; k < 32; k++) {
            int h  = hbase + k;
            int dh = row - h;
            int gv = (int)__ldcg(&g_G[h * W + j]);   // coalesced u16, MLP=32
            best = min(best, dh * dh + gv);
        }
        s_part[p][j] = best;
    }
    __syncthreads();

    if (tid < 128) {
        int b4 = min(min(s_part[0][j], s_part[1][j]),
                     min(s_part[2][j], s_part[3][j]));
        s_res[j] = (b4 > MAX_D2) ? INFINITY : sqrtf((float)b4);
    }
    __syncthreads();
    {
        float r = s_res[j];
        out[(2 * p)     * (H * W) + row * W + j] = r;
        out[(2 * p + 1) * (H * W) + row * W + j] = r;
    }
}

extern "C" void kernel_launch(void* const* d_in, const int* in_sizes, int n_in,
                              void* d_out, int out_size) {
    const float* in = (const float*)d_in[0];
    float* out = (float*)d_out;

    edt_g<<<H, 128>>>(in);

    // Secondary with programmatic dependent launch: its ramp overlaps K1.
    cudaLaunchConfig_t cfg = {};
    cfg.gridDim  = dim3(H, 1, 1);
    cfg.blockDim = dim3(512, 1, 1);
    cfg.dynamicSmemBytes = 0;
    cfg.stream = 0;   // same (legacy default) stream as K1 for capture order
    cudaLaunchAttribute attr[1];
    attr[0].id = cudaLaunchAttributeProgrammaticStreamSerialization;
    attr[0].val.programmaticStreamSerializationAllowed = 1;
    cfg.attrs = attr;
    cfg.numAttrs = 1;
    cudaLaunchKernelEx(&cfg, edt_d, out);
}